// round 5
// baseline (speedup 1.0000x reference)
#include <cuda_runtime.h>
#include <cuda_bf16.h>

// CenterLoss == per-row gathered squared distance:
// loss = [ sum_b clip(||x_b - c_{l_b}||^2, 1e-12, 1e12) + B*(C-1)*1e-12 ] / B
//
// Inputs: x [B, D] f32, labels [B] int32, centers [C, D] f32. Output: scalar f32.
//
// R5: 512 CTAs x 256 thr, one warp per row (4096 warps, one wave).
// - label read as uniform broadcast LDG (no shfl on the critical path)
// - 8 independent float4 LDGs per thread (x then centers)
// - block partial -> atomicAdd into one of 32 scattered slots (128B stride)
//   to avoid the end-of-kernel same-address LTS atomic convoy
// - last CTA (atomicInc) folds slots + clip-constant, writes out, resets.

#define BATCH 4096
#define FEAT 512
#define NCLASSES 10000
#define WARPS_PER_BLOCK 8
#define NBLOCKS (BATCH / WARPS_PER_BLOCK)   // 512
#define NSLOTS 32

__device__ float g_part[NSLOTS * 32];        // use every 32nd float: 128B stride
__device__ unsigned int g_count = 0;

__global__ __launch_bounds__(256) void center_loss_kernel(
    const float* __restrict__ x,
    const int* __restrict__ labels,
    const float* __restrict__ centers,
    float* __restrict__ out)
{
    const int tid  = threadIdx.x;
    const int warp = tid >> 5;
    const int lane = tid & 31;
    const int row  = blockIdx.x * WARPS_PER_BLOCK + warp;

    // uniform broadcast load: every lane, same address -> 1 wavefront, no shfl
    int lbl = labels[row];
    lbl = min(max(lbl, 0), NCLASSES - 1);

    const float4* xr = reinterpret_cast<const float4*>(x + (size_t)row * FEAT);
    const float4* cr = reinterpret_cast<const float4*>(centers + (size_t)lbl * FEAT);

    float4 xv[4], cv[4];
#pragma unroll
    for (int i = 0; i < 4; i++) xv[i] = xr[lane + 32 * i];
#pragma unroll
    for (int i = 0; i < 4; i++) cv[i] = cr[lane + 32 * i];

    float s = 0.0f;
#pragma unroll
    for (int i = 0; i < 4; i++) {
        float d0 = xv[i].x - cv[i].x;
        float d1 = xv[i].y - cv[i].y;
        float d2 = xv[i].z - cv[i].z;
        float d3 = xv[i].w - cv[i].w;
        s += d0 * d0 + d1 * d1 + d2 * d2 + d3 * d3;
    }

#pragma unroll
    for (int off = 16; off > 0; off >>= 1)
        s += __shfl_xor_sync(0xFFFFFFFFu, s, off);

    __shared__ float warp_sums[WARPS_PER_BLOCK];
    if (lane == 0) {
        // faithful per-entry clamp of the true-class distance
        warp_sums[warp] = fminf(fmaxf(s, 1e-12f), 1e12f);
    }
    __syncthreads();

    if (warp == 0) {
        float p = (lane < WARPS_PER_BLOCK) ? warp_sums[lane] : 0.0f;
#pragma unroll
        for (int off = 4; off > 0; off >>= 1)
            p += __shfl_xor_sync(0xFFFFFFFFu, p, off);

        if (lane == 0) {
            // scatter across 32 slots, 128B apart (distinct LTS lines)
            atomicAdd(&g_part[(blockIdx.x & (NSLOTS - 1)) * 32], p);
            __threadfence();
            unsigned done = atomicInc(&g_count, NBLOCKS - 1); // wraps to 0 on last
            if (done == NBLOCKS - 1) {
                float total = 0.0f;
#pragma unroll
                for (int i = 0; i < NSLOTS; i++) {
                    volatile float* slot = &g_part[i * 32];
                    total += *slot;
                    *slot = 0.0f;   // reset for next graph replay
                }
                out[0] = total * (1.0f / (float)BATCH)
                       + (float)((double)(NCLASSES - 1) * 1e-12);
                __threadfence();
            }
        }
    }
}

extern "C" void kernel_launch(void* const* d_in, const int* in_sizes, int n_in,
                              void* d_out, int out_size) {
    const float* x = (const float*)d_in[0];
    const int* labels = (const int*)d_in[1];
    const float* centers = (const float*)d_in[2];
    float* out = (float*)d_out;

    center_loss_kernel<<<NBLOCKS, 256>>>(x, labels, centers, out);
}

// round 6
// speedup vs baseline: 1.2444x; 1.2444x over previous
#include <cuda_runtime.h>
#include <cuda_bf16.h>

// CenterLoss == per-row gathered squared distance:
// loss = [ sum_b clip(||x_b - c_{l_b}||^2, 1e-12, 1e12) + B*(C-1)*1e-12 ] / B
//
// Inputs: x [B, D] f32, labels [B] int32, centers [C, D] f32. Output: scalar f32.
//
// R6: software-pipelined, 4 rows per warp.
//  - prologue issues all labels + all x tiles (independent), then centers[0]
//  - loop overlaps centers[r+1] load with row-r compute
//  - 256 CTAs x 128 thr (1024 warps); per-warp cost ~1 latency epoch + 4 cheap iters
//  - scattered-slot atomic epilogue; last block does a parallel slot reduce.

#define BATCH 4096
#define FEAT 512
#define NCLASSES 10000
#define ROWS_PER_WARP 4
#define THREADS 128
#define WARPS_PER_BLOCK 4
#define NBLOCKS (BATCH / (ROWS_PER_WARP * WARPS_PER_BLOCK))   // 256
#define NSLOTS 32

__device__ float g_part[NSLOTS * 32];        // every 32nd float: 128B stride
__device__ unsigned int g_count = 0;

__global__ __launch_bounds__(THREADS) void center_loss_kernel(
    const float* __restrict__ x,
    const int* __restrict__ labels,
    const float* __restrict__ centers,
    float* __restrict__ out)
{
    const int tid  = threadIdx.x;
    const int warp = tid >> 5;
    const int lane = tid & 31;
    const int wg   = blockIdx.x * WARPS_PER_BLOCK + warp;   // 0..1023
    const int row0 = wg * ROWS_PER_WARP;

    // ---- prologue: all labels (uniform broadcast) + all x tiles ----
    int lab[ROWS_PER_WARP];
#pragma unroll
    for (int r = 0; r < ROWS_PER_WARP; r++)
        lab[r] = labels[row0 + r];

    float4 xv[ROWS_PER_WARP][4];
#pragma unroll
    for (int r = 0; r < ROWS_PER_WARP; r++) {
        const float4* xr = reinterpret_cast<const float4*>(x + (size_t)(row0 + r) * FEAT);
#pragma unroll
        for (int i = 0; i < 4; i++) xv[r][i] = xr[lane + 32 * i];
    }

    // centers[0] issued as soon as lab[0] lands (x loads still in flight)
    float4 cv[2][4];
    {
        int l0 = min(max(lab[0], 0), NCLASSES - 1);
        const float4* cr = reinterpret_cast<const float4*>(centers + (size_t)l0 * FEAT);
#pragma unroll
        for (int i = 0; i < 4; i++) cv[0][i] = cr[lane + 32 * i];
    }

    // ---- pipelined loop: issue centers[r+1], compute row r ----
    float s[ROWS_PER_WARP];
#pragma unroll
    for (int r = 0; r < ROWS_PER_WARP; r++) {
        if (r + 1 < ROWS_PER_WARP) {
            int ln = min(max(lab[r + 1], 0), NCLASSES - 1);
            const float4* cr = reinterpret_cast<const float4*>(centers + (size_t)ln * FEAT);
#pragma unroll
            for (int i = 0; i < 4; i++) cv[(r + 1) & 1][i] = cr[lane + 32 * i];
        }
        float acc = 0.0f;
#pragma unroll
        for (int i = 0; i < 4; i++) {
            float4 a = xv[r][i];
            float4 c = cv[r & 1][i];
            float d0 = a.x - c.x, d1 = a.y - c.y;
            float d2 = a.z - c.z, d3 = a.w - c.w;
            acc += d0 * d0 + d1 * d1 + d2 * d2 + d3 * d3;
        }
        s[r] = acc;
    }

    // ---- warp reduce all 4 rows (interleaved butterflies) ----
#pragma unroll
    for (int off = 16; off > 0; off >>= 1) {
#pragma unroll
        for (int r = 0; r < ROWS_PER_WARP; r++)
            s[r] += __shfl_xor_sync(0xFFFFFFFFu, s[r], off);
    }

    __shared__ float warp_sums[WARPS_PER_BLOCK];
    if (lane == 0) {
        // faithful per-entry clamp BEFORE summation
        float p = 0.0f;
#pragma unroll
        for (int r = 0; r < ROWS_PER_WARP; r++)
            p += fminf(fmaxf(s[r], 1e-12f), 1e12f);
        warp_sums[warp] = p;
    }
    __syncthreads();

    if (warp == 0) {
        float p = (lane < WARPS_PER_BLOCK) ? warp_sums[lane] : 0.0f;
#pragma unroll
        for (int off = 2; off > 0; off >>= 1)
            p += __shfl_xor_sync(0xFFFFFFFFu, p, off);

        unsigned done = 0;
        if (lane == 0) {
            atomicAdd(&g_part[(blockIdx.x & (NSLOTS - 1)) * 32], p);
            __threadfence();
            done = (atomicInc(&g_count, NBLOCKS - 1) == NBLOCKS - 1) ? 1u : 0u;
        }
        done = __shfl_sync(0xFFFFFFFFu, done, 0);

        if (done) {
            // parallel slot reduce: lane i reads slot i (independent LDGs)
            volatile float* slot = &g_part[lane * 32];
            float t = *slot;
            *slot = 0.0f;                       // parallel reset for next replay
#pragma unroll
            for (int off = 16; off > 0; off >>= 1)
                t += __shfl_xor_sync(0xFFFFFFFFu, t, off);
            if (lane == 0) {
                out[0] = t * (1.0f / (float)BATCH)
                       + (float)((double)(NCLASSES - 1) * 1e-12);
                __threadfence();
            }
        }
    }
}

extern "C" void kernel_launch(void* const* d_in, const int* in_sizes, int n_in,
                              void* d_out, int out_size) {
    const float* x = (const float*)d_in[0];
    const int* labels = (const int*)d_in[1];
    const float* centers = (const float*)d_in[2];
    float* out = (float*)d_out;

    center_loss_kernel<<<NBLOCKS, THREADS>>>(x, labels, centers, out);
}

// round 7
// speedup vs baseline: 1.2584x; 1.0112x over previous
#include <cuda_runtime.h>
#include <cuda_bf16.h>

// CenterLoss == per-row gathered squared distance:
// loss = [ sum_b clip(||x_b - c_{l_b}||^2, 1e-12, 1e12) + B*(C-1)*1e-12 ] / B
//
// Inputs: x [B, D] f32, labels [B] int32, centers [C, D] f32. Output: scalar f32.
//
// R7: max concurrency on BOTH axes. 1024 CTAs x 256 thr (one full wave,
// ~1792 thr/SM), 4 rows/CTA with 64 threads/row, each thread 2 x-float4 +
// 2 c-float4 (MLP=4). Scattered-slot atomic epilogue, last CTA reduces.

#define BATCH 4096
#define FEAT 512
#define NCLASSES 10000
#define THREADS 256
#define ROWS_PER_CTA 4
#define NBLOCKS (BATCH / ROWS_PER_CTA)   // 1024
#define NSLOTS 32

__device__ float g_part[NSLOTS * 32];    // every 32nd float: 128B stride
__device__ unsigned int g_count = 0;

__global__ __launch_bounds__(THREADS) void center_loss_kernel(
    const float* __restrict__ x,
    const int* __restrict__ labels,
    const float* __restrict__ centers,
    float* __restrict__ out)
{
    const int tid    = threadIdx.x;
    const int warp   = tid >> 5;          // 0..7
    const int lane   = tid & 31;
    const int rid    = tid >> 6;          // row within CTA: 0..3 (2 warps/row)
    const int lane64 = tid & 63;          // thread within row
    const int row    = blockIdx.x * ROWS_PER_CTA + rid;

    // label: uniform across the 64-thread row group -> broadcast LDG
    int lbl = labels[row];
    lbl = min(max(lbl, 0), NCLASSES - 1);

    // 512 floats = 128 float4 per row; 64 threads x 2 float4 each
    const float4* xr = reinterpret_cast<const float4*>(x + (size_t)row * FEAT);
    const float4* cr = reinterpret_cast<const float4*>(centers + (size_t)lbl * FEAT);

    float4 x0 = xr[lane64];
    float4 x1 = xr[lane64 + 64];
    float4 c0 = cr[lane64];
    float4 c1 = cr[lane64 + 64];

    float d0 = x0.x - c0.x, d1 = x0.y - c0.y, d2 = x0.z - c0.z, d3 = x0.w - c0.w;
    float e0 = x1.x - c1.x, e1 = x1.y - c1.y, e2 = x1.z - c1.z, e3 = x1.w - c1.w;
    float s = d0 * d0 + d1 * d1 + d2 * d2 + d3 * d3
            + e0 * e0 + e1 * e1 + e2 * e2 + e3 * e3;

    // warp reduce
#pragma unroll
    for (int off = 16; off > 0; off >>= 1)
        s += __shfl_xor_sync(0xFFFFFFFFu, s, off);

    __shared__ float warp_sums[8];
    if (lane == 0) warp_sums[warp] = s;
    __syncthreads();

    if (warp == 0) {
        // row r = warp_sums[2r] + warp_sums[2r+1]; clamp per row, then sum
        float p = 0.0f;
        if (lane < ROWS_PER_CTA) {
            float d = warp_sums[2 * lane] + warp_sums[2 * lane + 1];
            p = fminf(fmaxf(d, 1e-12f), 1e12f);   // faithful per-entry clamp
        }
#pragma unroll
        for (int off = 2; off > 0; off >>= 1)
            p += __shfl_xor_sync(0xFFFFFFFFu, p, off);

        unsigned done = 0;
        if (lane == 0) {
            atomicAdd(&g_part[(blockIdx.x & (NSLOTS - 1)) * 32], p);
            __threadfence();
            done = (atomicInc(&g_count, NBLOCKS - 1) == NBLOCKS - 1) ? 1u : 0u;
        }
        done = __shfl_sync(0xFFFFFFFFu, done, 0);

        if (done) {
            // parallel slot reduce: lane i owns slot i
            volatile float* slot = &g_part[lane * 32];
            float t = *slot;
            *slot = 0.0f;                 // reset for next graph replay
#pragma unroll
            for (int off = 16; off > 0; off >>= 1)
                t += __shfl_xor_sync(0xFFFFFFFFu, t, off);
            if (lane == 0) {
                out[0] = t * (1.0f / (float)BATCH)
                       + (float)((double)(NCLASSES - 1) * 1e-12);
                __threadfence();
            }
        }
    }
}

extern "C" void kernel_launch(void* const* d_in, const int* in_sizes, int n_in,
                              void* d_out, int out_size) {
    const float* x = (const float*)d_in[0];
    const int* labels = (const int*)d_in[1];
    const float* centers = (const float*)d_in[2];
    float* out = (float*)d_out;

    center_loss_kernel<<<NBLOCKS, THREADS>>>(x, labels, centers, out);
}